// round 10
// baseline (speedup 1.0000x reference)
#include <cuda_runtime.h>
#include <cuda_bf16.h>
#include <math.h>
#include <stdint.h>

#define DM 1024
#define NH 16
#define DK 64
#define B_ 2
#define S_ 2048
#define MTOT (B_*S_)   // 4096

// ---------------- scratch (device globals: allocation-free) ----------------
__device__ float2 g_cs[S_ * (DK/2)];
__device__ __nv_bfloat16 g_xhi[MTOT*DM];
__device__ __nv_bfloat16 g_xlo[MTOT*DM];
__device__ __nv_bfloat16 g_whi[4][DM*DM];
__device__ __nv_bfloat16 g_wlo[4][DM*DM];
__device__ __nv_bfloat16 g_qhi[MTOT*DM];
__device__ __nv_bfloat16 g_qlo[MTOT*DM];
__device__ __nv_bfloat16 g_khi[MTOT*DM];
__device__ __nv_bfloat16 g_klo[MTOT*DM];
__device__ __nv_bfloat16 g_vhi[MTOT*DM];
__device__ __nv_bfloat16 g_vlo[MTOT*DM];

// ---------------- family-portable PTX helpers ----------------
__device__ __forceinline__ uint32_t smem_u32(const void* p) {
    uint32_t a;
    asm("{ .reg .u64 t; cvta.to.shared.u64 t, %1; cvt.u32.u64 %0, t; }"
        : "=r"(a) : "l"(p));
    return a;
}
#define CP16(saddr, gptr) \
    asm volatile("cp.async.cg.shared.global [%0], [%1], 16;" :: "r"(saddr), "l"(gptr))
#define CPCOMMIT() asm volatile("cp.async.commit_group;" ::: "memory")
#define CPWAIT0()  asm volatile("cp.async.wait_group 0;" ::: "memory")
#define CPWAIT1()  asm volatile("cp.async.wait_group 1;" ::: "memory")
#define LDSM4(r, addr) \
    asm volatile("ldmatrix.sync.aligned.m8n8.x4.shared.b16 {%0,%1,%2,%3}, [%4];" \
        : "=r"((r)[0]), "=r"((r)[1]), "=r"((r)[2]), "=r"((r)[3]) : "r"(addr))
#define LDSM4T(r, addr) \
    asm volatile("ldmatrix.sync.aligned.m8n8.x4.trans.shared.b16 {%0,%1,%2,%3}, [%4];" \
        : "=r"((r)[0]), "=r"((r)[1]), "=r"((r)[2]), "=r"((r)[3]) : "r"(addr))
#define MMA_BF16(d, a, b) \
    asm volatile("mma.sync.aligned.m16n8k16.row.col.f32.bf16.bf16.f32 " \
        "{%0,%1,%2,%3},{%4,%5,%6,%7},{%8,%9},{%0,%1,%2,%3};" \
        : "+f"((d)[0]), "+f"((d)[1]), "+f"((d)[2]), "+f"((d)[3]) \
        : "r"((a)[0]), "r"((a)[1]), "r"((a)[2]), "r"((a)[3]), \
          "r"((b)[0]), "r"((b)[1]))

__device__ __forceinline__ float ex2f(float x) {
    float y; asm("ex2.approx.ftz.f32 %0, %1;" : "=f"(y) : "f"(x)); return y;
}
__device__ __forceinline__ void split2(float v0, float v1, uint32_t& hi, uint32_t& lo) {
    uint32_t h;
    asm("cvt.rn.bf16x2.f32 %0, %1, %2;" : "=r"(h) : "f"(v1), "f"(v0));
    float h0 = __uint_as_float(h << 16);
    float h1 = __uint_as_float(h & 0xffff0000u);
    asm("cvt.rn.bf16x2.f32 %0, %1, %2;" : "=r"(lo) : "f"(v1 - h1), "f"(v0 - h0));
    hi = h;
}

#define SC2A (0.125f * 1.4426950408889634f)

// ---------------------------------------------------------------------------
__global__ void build_cs_kernel(const int* __restrict__ pos, float2* __restrict__ cs)
{
    int idx = blockIdx.x * blockDim.x + threadIdx.x;
    if (idx >= S_ * (DK/2)) return;
    int s = idx >> 5, p = idx & 31;
    float posf = (float)pos[s];
    double e   = (double)(2 * p) / (double)DK;
    float inv  = (float)exp(-e * log(10000.0));
    float ang  = posf * inv;
    cs[idx] = make_float2((float)cos((double)ang), (float)sin((double)ang));
}

__global__ void split_kernel(const float* __restrict__ src,
                             __nv_bfloat16* __restrict__ hi,
                             __nv_bfloat16* __restrict__ lo, int n)
{
    int i = (blockIdx.x * blockDim.x + threadIdx.x) * 8;
    if (i >= n) return;
    float4 a = *(const float4*)(src + i);
    float4 b = *(const float4*)(src + i + 4);
    float v[8] = {a.x, a.y, a.z, a.w, b.x, b.y, b.z, b.w};
    uint4 hp, lp;
    uint32_t* hw = (uint32_t*)&hp;
    uint32_t* lw = (uint32_t*)&lp;
#pragma unroll
    for (int j = 0; j < 4; j++) split2(v[2*j], v[2*j+1], hw[j], lw[j]);
    *(uint4*)((unsigned short*)hi + i) = hp;
    *(uint4*)((unsigned short*)lo + i) = lp;
}

__global__ void split_w_kernel(const float* __restrict__ Wq, const float* __restrict__ Wk,
                               const float* __restrict__ Wv, const float* __restrict__ Wo,
                               __nv_bfloat16* __restrict__ whi, __nv_bfloat16* __restrict__ wlo)
{
    int gid = blockIdx.x * blockDim.x + threadIdx.x;
    int w = gid >> 17;
    size_t i = (size_t)(gid & 131071) * 8;
    const float* src = (w == 0) ? Wq : (w == 1) ? Wk : (w == 2) ? Wv : Wo;
    size_t base = (size_t)w * DM * DM + i;
    float4 a = *(const float4*)(src + i);
    float4 b = *(const float4*)(src + i + 4);
    float v[8] = {a.x, a.y, a.z, a.w, b.x, b.y, b.z, b.w};
    uint4 hp, lp;
    uint32_t* hw = (uint32_t*)&hp;
    uint32_t* lw = (uint32_t*)&lp;
#pragma unroll
    for (int j = 0; j < 4; j++) split2(v[2*j], v[2*j+1], hw[j], lw[j]);
    *(uint4*)((unsigned short*)whi + base) = hp;
    *(uint4*)((unsigned short*)wlo + base) = lp;
}

// ---------------------------------------------------------------------------
// Split-bf16 GEMM. CTA tile 128x64, BK=32, 4 warps (64x32 each).
// 3-stage cp.async pipeline, ONE __syncthreads per iteration.
// ---------------------------------------------------------------------------
#define BKK 32
#define NKB (DM / BKK)
#define SROW 40
#define A_TILE (128 * SROW * 2)
#define B_TILE (64 * SROW * 2)
#define STAGE_BYTES (2 * A_TILE + 2 * B_TILE)   // 30720
#define GSMEM (3 * STAGE_BYTES)                 // 92160
#define OFF_AH 0
#define OFF_AL A_TILE
#define OFF_BH (2 * A_TILE)
#define OFF_BL (2 * A_TILE + B_TILE)

#define GEMM_PROLOG()                                                         \
    extern __shared__ char sm[];                                              \
    const uint32_t sb = smem_u32(sm);                                         \
    const int tid  = threadIdx.x;                                             \
    const int lane = tid & 31;                                                \
    const int wid  = tid >> 5;                                                \
    const int wm   = (wid & 1) * 64;                                          \
    const int wn   = (wid >> 1) * 32;                                         \
    const int m0   = blockIdx.y * 128;                                        \
    const int n0   = blockIdx.x * 64;

#define LOAD_STAGE(sidx, kb) do {                                             \
    uint32_t sdst = sb + (sidx) * STAGE_BYTES;                                \
    int kofs = (kb) * BKK;                                                    \
    _Pragma("unroll")                                                         \
    for (int i = 0; i < 4; i++) {                                             \
        int id = tid + i * 128;                                               \
        int r = id >> 2, c = (id & 3) * 8;                                    \
        CP16(sdst + OFF_AH + (r * SROW + c) * 2,                              \
             Ahi_ + (size_t)(m0 + r) * DM + kofs + c);                        \
        CP16(sdst + OFF_AL + (r * SROW + c) * 2,                              \
             Alo_ + (size_t)(m0 + r) * DM + kofs + c);                        \
    }                                                                         \
    _Pragma("unroll")                                                         \
    for (int i = 0; i < 2; i++) {                                             \
        int id = tid + i * 128;                                               \
        int r = id >> 2, c = (id & 3) * 8;                                    \
        CP16(sdst + OFF_BH + (r * SROW + c) * 2,                              \
             Bhi_ + (size_t)(n0 + r) * DM + kofs + c);                        \
        CP16(sdst + OFF_BL + (r * SROW + c) * 2,                              \
             Blo_ + (size_t)(n0 + r) * DM + kofs + c);                        \
    }                                                                         \
} while (0)

#define GEMM_MAIN()                                                           \
    float acc[4][4][4];                                                       \
    _Pragma("unroll")                                                         \
    for (int i = 0; i < 4; i++)                                               \
        _Pragma("unroll")                                                     \
        for (int j = 0; j < 4; j++)                                           \
            _Pragma("unroll")                                                 \
            for (int q = 0; q < 4; q++) acc[i][j][q] = 0.f;                   \
    LOAD_STAGE(0, 0);                                                         \
    CPCOMMIT();                                                               \
    LOAD_STAGE(1, 1);                                                         \
    CPCOMMIT();                                                               \
    int st = 0;                                                               \
    for (int kb = 0; kb < NKB; kb++) {                                        \
        if (kb + 1 < NKB) CPWAIT1(); else CPWAIT0();                          \
        __syncthreads();   /* all warps done reading stage kb-1 */            \
        if (kb + 2 < NKB) {                                                   \
            int wsl = st + 2; if (wsl >= 3) wsl -= 3;                         \
            LOAD_STAGE(wsl, kb + 2);                                          \
            CPCOMMIT();                                                       \
        }                                                                     \
        const uint32_t sst = sb + st * STAGE_BYTES;                           \
        _Pragma("unroll")                                                     \
        for (int kk = 0; kk < 2; kk++) {                                      \
            uint32_t a_hi[4][4], a_lo[4][4], b_h[2][4], b_l[2][4];            \
            const int ar = wm + (lane & 15);                                  \
            const int ac = kk * 16 + (lane >> 4) * 8;                         \
            _Pragma("unroll")                                                 \
            for (int i = 0; i < 4; i++) {                                     \
                uint32_t ad = sst + (((ar + i * 16) * SROW + ac) << 1);       \
                LDSM4(a_hi[i], ad + OFF_AH);                                  \
                LDSM4(a_lo[i], ad + OFF_AL);                                  \
            }                                                                 \
            const int br = wn + ((lane >> 4) << 3) + (lane & 7);              \
            const int bc = kk * 16 + ((lane >> 3) & 1) * 8;                   \
            _Pragma("unroll")                                                 \
            for (int nb = 0; nb < 2; nb++) {                                  \
                uint32_t bd = sst + (((br + nb * 16) * SROW + bc) << 1);      \
                LDSM4(b_h[nb], bd + OFF_BH);                                  \
                LDSM4(b_l[nb], bd + OFF_BL);                                  \
            }                                                                 \
            _Pragma("unroll")                                                 \
            for (int nb = 0; nb < 2; nb++)                                    \
                _Pragma("unroll")                                             \
                for (int i = 0; i < 4; i++) {                                 \
                    MMA_BF16(acc[i][2*nb],   a_hi[i], &b_h[nb][0]);           \
                    MMA_BF16(acc[i][2*nb+1], a_hi[i], &b_h[nb][2]);           \
                }                                                             \
            _Pragma("unroll")                                                 \
            for (int nb = 0; nb < 2; nb++)                                    \
                _Pragma("unroll")                                             \
                for (int i = 0; i < 4; i++) {                                 \
                    MMA_BF16(acc[i][2*nb],   a_hi[i], &b_l[nb][0]);           \
                    MMA_BF16(acc[i][2*nb+1], a_hi[i], &b_l[nb][2]);           \
                }                                                             \
            _Pragma("unroll")                                                 \
            for (int nb = 0; nb < 2; nb++)                                    \
                _Pragma("unroll")                                             \
                for (int i = 0; i < 4; i++) {                                 \
                    MMA_BF16(acc[i][2*nb],   a_lo[i], &b_h[nb][0]);           \
                    MMA_BF16(acc[i][2*nb+1], a_lo[i], &b_h[nb][2]);           \
                }                                                             \
        }                                                                     \
        if (++st >= 3) st -= 3;                                               \
    }

// ---- QKV projections in ONE launch: blockIdx.z = 0(Q) 1(K) 2(V)
__global__ __launch_bounds__(128, 2)
void gemm_qkv(const __nv_bfloat16* __restrict__ Xhi, const __nv_bfloat16* __restrict__ Xlo,
              const __nv_bfloat16* __restrict__ Whi, const __nv_bfloat16* __restrict__ Wlo,
              __nv_bfloat16* __restrict__ qhi, __nv_bfloat16* __restrict__ qlo,
              __nv_bfloat16* __restrict__ khi, __nv_bfloat16* __restrict__ klo,
              __nv_bfloat16* __restrict__ vhi, __nv_bfloat16* __restrict__ vlo,
              const float2* __restrict__ cs)
{
    GEMM_PROLOG();
    const int z = blockIdx.z;
    const __nv_bfloat16* Ahi_ = Xhi;
    const __nv_bfloat16* Alo_ = Xlo;
    const __nv_bfloat16* Bhi_ = Whi + (size_t)z * DM * DM;
    const __nv_bfloat16* Blo_ = Wlo + (size_t)z * DM * DM;
    GEMM_MAIN();

    __nv_bfloat16* Yhi = (z == 0) ? qhi : (z == 1) ? khi : vhi;
    __nv_bfloat16* Ylo = (z == 0) ? qlo : (z == 1) ? klo : vlo;
#pragma unroll
    for (int i = 0; i < 4; i++)
#pragma unroll
        for (int j = 0; j < 4; j++) {
            const int col = n0 + wn + j * 8 + (lane & 3) * 2;
#pragma unroll
            for (int h = 0; h < 2; h++) {
                const int row = m0 + wm + i * 16 + (lane >> 2) + h * 8;
                float v0 = acc[i][j][h * 2], v1 = acc[i][j][h * 2 + 1];
                if (z < 2) {
                    int s = row & (S_ - 1);
                    float2 cp = cs[s * 32 + ((col & (DK - 1)) >> 1)];
                    float o0 = v0 * cp.x - v1 * cp.y;
                    float o1 = v0 * cp.y + v1 * cp.x;
                    v0 = o0; v1 = o1;
                }
                if (z == 0) { v0 *= SC2A; v1 *= SC2A; }
                uint32_t hp, lp;
                split2(v0, v1, hp, lp);
                *(uint32_t*)((unsigned short*)Yhi + (size_t)row * DM + col) = hp;
                *(uint32_t*)((unsigned short*)Ylo + (size_t)row * DM + col) = lp;
            }
        }
}

__global__ __launch_bounds__(128, 2)
void gemm_o(const __nv_bfloat16* __restrict__ Xhi, const __nv_bfloat16* __restrict__ Xlo,
            const __nv_bfloat16* __restrict__ Whi, const __nv_bfloat16* __restrict__ Wlo,
            float* __restrict__ Y)
{
    GEMM_PROLOG();
    const __nv_bfloat16* Ahi_ = Xhi;
    const __nv_bfloat16* Alo_ = Xlo;
    const __nv_bfloat16* Bhi_ = Whi;
    const __nv_bfloat16* Blo_ = Wlo;
    GEMM_MAIN();

#pragma unroll
    for (int i = 0; i < 4; i++)
#pragma unroll
        for (int j = 0; j < 4; j++) {
            const int col = n0 + wn + j * 8 + (lane & 3) * 2;
#pragma unroll
            for (int h = 0; h < 2; h++) {
                const int row = m0 + wm + i * 16 + (lane >> 2) + h * 8;
                *(float2*)(Y + (size_t)row * DM + col) =
                    make_float2(acc[i][j][h * 2], acc[i][j][h * 2 + 1]);
            }
        }
}

// ---------------------------------------------------------------------------
// Tensor-core causal flash attention, split bf16, 3-stage KV pipeline,
// single __syncthreads per k-block. Q pre-scaled by 0.125*log2e.
// ---------------------------------------------------------------------------
#define SP 72
#define QBB (128 * SP * 2)
#define KVB (64 * SP * 2)
#define STG (4 * KVB)
#define ATT_SMEM (2 * QBB + 3 * STG)   // 147456

__global__ __launch_bounds__(256)
void attn_mma(const __nv_bfloat16* __restrict__ Qhi, const __nv_bfloat16* __restrict__ Qlo,
              const __nv_bfloat16* __restrict__ Khi, const __nv_bfloat16* __restrict__ Klo,
              const __nv_bfloat16* __restrict__ Vhi, const __nv_bfloat16* __restrict__ Vlo,
              __nv_bfloat16* __restrict__ Ahi, __nv_bfloat16* __restrict__ Alo)
{
    extern __shared__ char sm[];
    const uint32_t sb = smem_u32(sm);
    const uint32_t sQh = sb, sQl = sb + QBB;
    const uint32_t sStage = sb + 2 * QBB;

    const int tid = threadIdx.x, lane = tid & 31, wid = tid >> 5;
    const int qb = 15 - blockIdx.x;
    const int bh = blockIdx.y;
    const int b = bh >> 4, h = bh & 15;
    const int wm = wid * 16;
    const size_t rowbase = (size_t)b * S_;
    const int hoff = h * DK;

    // Q tile (goes into first commit group)
#pragma unroll
    for (int i = 0; i < 4; i++) {
        int id = tid + i * 256;
        int r = id >> 3, c = (id & 7) * 8;
        size_t g = (rowbase + qb * 128 + r) * DM + hoff + c;
        uint32_t so = (r * SP + c) * 2;
        CP16(sQh + so, Qhi + g);
        CP16(sQl + so, Qlo + g);
    }

#define LOAD_KV(sidx, kb_) do {                                               \
    uint32_t dst = sStage + (sidx) * STG;                                     \
    size_t krow0 = rowbase + (size_t)(kb_) * 64;                              \
    _Pragma("unroll")                                                         \
    for (int i = 0; i < 2; i++) {                                             \
        int id = tid + i * 256;                                               \
        int r = id >> 3, c = (id & 7) * 8;                                    \
        size_t g = (krow0 + r) * DM + hoff + c;                               \
        uint32_t so = (r * SP + c) * 2;                                       \
        CP16(dst + 0 * KVB + so, Khi + g);                                    \
        CP16(dst + 1 * KVB + so, Klo + g);                                    \
        CP16(dst + 2 * KVB + so, Vhi + g);                                    \
        CP16(dst + 3 * KVB + so, Vlo + g);                                    \
    }                                                                         \
} while (0)

    const int nkb = 2 * qb + 2;
    LOAD_KV(0, 0);
    CPCOMMIT();
    if (nkb > 1) { LOAD_KV(1, 1); CPCOMMIT(); }

    float m2[2] = {-1e30f, -1e30f}, l[2] = {0.f, 0.f};
    float oacc[8][4];
#pragma unroll
    for (int j = 0; j < 8; j++)
#pragma unroll
        for (int q = 0; q < 4; q++) oacc[j][q] = 0.f;

    uint32_t qf_h[4][4], qf_l[4][4];

    const uint32_t q_off  = ((uint32_t)(wm + (lane & 15)) * SP + (lane >> 4) * 8) * 2;
    const uint32_t k_loff = ((uint32_t)(((lane >> 4) << 3) + (lane & 7)) * SP
                             + ((lane >> 3) & 1) * 8) * 2;
    const uint32_t v_loff = ((uint32_t)(lane & 15) * SP + (lane >> 4) * 8) * 2;

    int st = 0;
    for (int kb = 0; kb < nkb; kb++) {
        if (kb + 1 < nkb) CPWAIT1(); else CPWAIT0();
        __syncthreads();   // all warps done reading stage kb-1
        if (kb + 2 < nkb) {
            int wsl = st + 2; if (wsl >= 3) wsl -= 3;
            LOAD_KV(wsl, kb + 2);
            CPCOMMIT();
        }

        if (kb == 0) {
#pragma unroll
            for (int kc = 0; kc < 4; kc++) {
                LDSM4(qf_h[kc], sQh + q_off + kc * 32);
                LDSM4(qf_l[kc], sQl + q_off + kc * 32);
            }
        }

        const uint32_t sK = sStage + st * STG;
        const uint32_t sV = sK + 2 * KVB;

        float sacc[8][4];
#pragma unroll
        for (int j = 0; j < 8; j++)
#pragma unroll
            for (int q = 0; q < 4; q++) sacc[j][q] = 0.f;

#pragma unroll
        for (int kc = 0; kc < 4; kc++) {
            uint32_t kb_h[4][4], kb_l[4][4];
#pragma unroll
            for (int nb = 0; nb < 4; nb++) {
                uint32_t ka = sK + (uint32_t)(nb * 16) * SP * 2 + k_loff + kc * 32;
                LDSM4(kb_h[nb], ka);
                LDSM4(kb_l[nb], ka + KVB);
            }
#pragma unroll
            for (int nb = 0; nb < 4; nb++) {
                MMA_BF16(sacc[2*nb],   qf_h[kc], &kb_h[nb][0]);
                MMA_BF16(sacc[2*nb+1], qf_h[kc], &kb_h[nb][2]);
            }
#pragma unroll
            for (int nb = 0; nb < 4; nb++) {
                MMA_BF16(sacc[2*nb],   qf_h[kc], &kb_l[nb][0]);
                MMA_BF16(sacc[2*nb+1], qf_h[kc], &kb_l[nb][2]);
            }
#pragma unroll
            for (int nb = 0; nb < 4; nb++) {
                MMA_BF16(sacc[2*nb],   qf_l[kc], &kb_h[nb][0]);
                MMA_BF16(sacc[2*nb+1], qf_l[kc], &kb_h[nb][2]);
            }
        }

        const int grow0 = qb * 128 + wm + (lane >> 2);
        const bool diag = (kb >= 2 * qb);
        float rmx0 = -1e30f, rmx1 = -1e30f;
        if (diag) {
#pragma unroll
            for (int j = 0; j < 8; j++) {
                int cbase = kb * 64 + j * 8 + 2 * (lane & 3);
#pragma unroll
                for (int e = 0; e < 2; e++) {
                    if (cbase + e > grow0)     sacc[j][e]     = -1e30f;
                    if (cbase + e > grow0 + 8) sacc[j][2 + e] = -1e30f;
                }
            }
        }
#pragma unroll
        for (int j = 0; j < 8; j++) {
            rmx0 = fmaxf(rmx0, fmaxf(sacc[j][0], sacc[j][1]));
            rmx1 = fmaxf(rmx1, fmaxf(sacc[j][2], sacc[j][3]));
        }
        rmx0 = fmaxf(rmx0, __shfl_xor_sync(0xffffffffu, rmx0, 1));
        rmx0 = fmaxf(rmx0, __shfl_xor_sync(0xffffffffu, rmx0, 2));
        rmx1 = fmaxf(rmx1, __shfl_xor_sync(0xffffffffu, rmx1, 1));
        rmx1 = fmaxf(rmx1, __shfl_xor_sync(0xffffffffu, rmx1, 2));
        float mn0 = fmaxf(m2[0], rmx0), mn1 = fmaxf(m2[1], rmx1);

        float rs0 = 0.f, rs1 = 0.f;
#pragma unroll
        for (int j = 0; j < 8; j++) {
#pragma unroll
            for (int e = 0; e < 2; e++) {
                float p0 = ex2f(sacc[j][e] - mn0);
                float p1 = ex2f(sacc[j][2 + e] - mn1);
                sacc[j][e] = p0; sacc[j][2 + e] = p1;
                rs0 += p0; rs1 += p1;
            }
        }
        rs0 += __shfl_xor_sync(0xffffffffu, rs0, 1);
        rs0 += __shfl_xor_sync(0xffffffffu, rs0, 2);
        rs1 += __shfl_xor_sync(0xffffffffu, rs1, 1);
        rs1 += __shfl_xor_sync(0xffffffffu, rs1, 2);

        float al0 = ex2f(m2[0] - mn0), al1 = ex2f(m2[1] - mn1);
        l[0] = l[0] * al0 + rs0;
        l[1] = l[1] * al1 + rs1;
        m2[0] = mn0; m2[1] = mn1;
#pragma unroll
        for (int j = 0; j < 8; j++) {
            oacc[j][0] *= al0; oacc[j][1] *= al0;
            oacc[j][2] *= al1; oacc[j][3] *= al1;
        }

#pragma unroll
        for (int g = 0; g < 4; g++) {
            uint32_t pa_h[4], pa_l[4];
            split2(sacc[2*g][0],   sacc[2*g][1],   pa_h[0], pa_l[0]);
            split2(sacc[2*g][2],   sacc[2*g][3],   pa_h[1], pa_l[1]);
            split2(sacc[2*g+1][0], sacc[2*g+1][1], pa_h[2], pa_l[2]);
            split2(sacc[2*g+1][2], sacc[2*g+1][3], pa_h[3], pa_l[3]);
            uint32_t vb_h[4][4], vb_l[4][4];
#pragma unroll
            for (int nb = 0; nb < 4; nb++) {
                uint32_t va = sV + (uint32_t)(g * 16) * SP * 2 + v_loff + nb * 32;
                LDSM4T(vb_h[nb], va);
                LDSM4T(vb_l[nb], va + KVB);
            }
#pragma unroll
            for (int nb = 0; nb < 4; nb++) {
                MMA_BF16(oacc[2*nb],   pa_h, &vb_h[nb][0]);
                MMA_BF16(oacc[2*nb+1], pa_h, &vb_h[nb][2]);
            }
#pragma unroll
            for (int nb = 0; nb < 4; nb++) {
                MMA_BF16(oacc[2*nb],   pa_h, &vb_l[nb][0]);
                MMA_BF16(oacc[2*nb+1], pa_h, &vb_l[nb][2]);
            }
#pragma unroll
            for (int nb = 0; nb < 4; nb++) {
                MMA_BF16(oacc[2*nb],   pa_l, &vb_h[nb][0]);
                MMA_BF16(oacc[2*nb+1], pa_l, &vb_h[nb][2]);
            }
        }
        if (++st >= 3) st -= 3;
    }
#undef LOAD_KV

    float inv0 = 1.f / l[0], inv1 = 1.f / l[1];
    const size_t row0 = rowbase + (size_t)qb * 128 + wm + (lane >> 2);
#pragma unroll
    for (int j = 0; j < 8; j++) {
        const int col = hoff + j * 8 + 2 * (lane & 3);
        uint32_t hp, lp;
        split2(oacc[j][0] * inv0, oacc[j][1] * inv0, hp, lp);
        *(uint32_t*)((unsigned short*)Ahi + row0 * DM + col) = hp;
        *(uint32_t*)((unsigned short*)Alo + row0 * DM + col) = lp;
        split2(oacc[j][2] * inv1, oacc[j][3] * inv1, hp, lp);
        *(uint32_t*)((unsigned short*)Ahi + (row0 + 8) * DM + col) = hp;
        *(uint32_t*)((unsigned short*)Alo + (row0 + 8) * DM + col) = lp;
    }
}

// ---------------------------------------------------------------------------
extern "C" void kernel_launch(void* const* d_in, const int* in_sizes, int n_in,
                              void* d_out, int out_size)
{
    const float *x, *Wq, *Wk, *Wv, *Wo;
    const int* pos;
    if (in_sizes[0] == MTOT * DM) {            // setup_inputs dict order
        x   = (const float*)d_in[0];
        pos = (const int*)  d_in[1];
        Wq  = (const float*)d_in[2];
        Wk  = (const float*)d_in[3];
        Wv  = (const float*)d_in[4];
        Wo  = (const float*)d_in[5];
    } else {                                   // name-sorted order
        Wk  = (const float*)d_in[0];
        Wo  = (const float*)d_in[1];
        Wq  = (const float*)d_in[2];
        Wv  = (const float*)d_in[3];
        pos = (const int*)  d_in[4];
        x   = (const float*)d_in[5];
    }
    float* out = (float*)d_out;

    float2* cs;
    __nv_bfloat16 *xhi, *xlo, *whi, *wlo, *qhi, *qlo, *khi, *klo, *vhi, *vlo;
    cudaGetSymbolAddress((void**)&cs,  g_cs);
    cudaGetSymbolAddress((void**)&xhi, g_xhi);
    cudaGetSymbolAddress((void**)&xlo, g_xlo);
    cudaGetSymbolAddress((void**)&whi, g_whi);
    cudaGetSymbolAddress((void**)&wlo, g_wlo);
    cudaGetSymbolAddress((void**)&qhi, g_qhi);
    cudaGetSymbolAddress((void**)&qlo, g_qlo);
    cudaGetSymbolAddress((void**)&khi, g_khi);
    cudaGetSymbolAddress((void**)&klo, g_klo);
    cudaGetSymbolAddress((void**)&vhi, g_vhi);
    cudaGetSymbolAddress((void**)&vlo, g_vlo);

    const int NX = MTOT * DM, NW = DM * DM;

    build_cs_kernel<<<(S_ * (DK/2) + 255) / 256, 256>>>(pos, cs);          // 0
    split_kernel<<<NX / 8 / 256, 256>>>(x, xhi, xlo, NX);                  // 1
    split_w_kernel<<<4 * NW / 8 / 256, 256>>>(Wq, Wk, Wv, Wo, whi, wlo);   // 2

    cudaFuncSetAttribute(gemm_qkv, cudaFuncAttributeMaxDynamicSharedMemorySize, GSMEM);
    cudaFuncSetAttribute(gemm_o,   cudaFuncAttributeMaxDynamicSharedMemorySize, GSMEM);
    cudaFuncSetAttribute(attn_mma, cudaFuncAttributeMaxDynamicSharedMemorySize, ATT_SMEM);

    dim3 gq(DM / 64, MTOT / 128, 3);    // (16, 32, 3)
    gemm_qkv<<<gq, 128, GSMEM>>>(xhi, xlo, whi, wlo,
                                 qhi, qlo, khi, klo, vhi, vlo, cs);        // 3

    attn_mma<<<dim3(16, B_ * NH), 256, ATT_SMEM>>>(qhi, qlo, khi, klo,
                                                   vhi, vlo, xhi, xlo);    // 4

    dim3 gg(DM / 64, MTOT / 128);       // (16, 32)
    gemm_o<<<gg, 128, GSMEM>>>(xhi, xlo, whi + 3 * (size_t)NW,
                               wlo + 3 * (size_t)NW, out);                 // 5 <- profiled
}

// round 12
// speedup vs baseline: 1.4692x; 1.4692x over previous
#include <cuda_runtime.h>
#include <cuda_fp16.h>
#include <math.h>
#include <stdint.h>

#define DM 1024
#define NH 16
#define DK 64
#define B_ 2
#define S_ 2048
#define MTOT (B_*S_)   // 4096

// ---------------- scratch (device globals: allocation-free) ----------------
// fp16 2-product scheme: activations single fp16, stationary operands hi+lo.
__device__ float2 g_cs[S_ * (DK/2)];
__device__ __half g_x[MTOT*DM];          // X fp16 single (reused for attn out A)
__device__ __half g_whi[4][DM*DM];
__device__ __half g_wlo[4][DM*DM];
__device__ __half g_q[MTOT*DM];          // Q fp16 single (pre-scaled)
__device__ __half g_khi[MTOT*DM];
__device__ __half g_klo[MTOT*DM];
__device__ __half g_vhi[MTOT*DM];
__device__ __half g_vlo[MTOT*DM];

// ---------------- family-portable PTX helpers ----------------
__device__ __forceinline__ uint32_t smem_u32(const void* p) {
    uint32_t a;
    asm("{ .reg .u64 t; cvta.to.shared.u64 t, %1; cvt.u32.u64 %0, t; }"
        : "=r"(a) : "l"(p));
    return a;
}
#define CP16(saddr, gptr) \
    asm volatile("cp.async.cg.shared.global [%0], [%1], 16;" :: "r"(saddr), "l"(gptr))
#define CPCOMMIT() asm volatile("cp.async.commit_group;" ::: "memory")
#define CPWAIT0()  asm volatile("cp.async.wait_group 0;" ::: "memory")
#define CPWAIT1()  asm volatile("cp.async.wait_group 1;" ::: "memory")
#define LDSM4(r, addr) \
    asm volatile("ldmatrix.sync.aligned.m8n8.x4.shared.b16 {%0,%1,%2,%3}, [%4];" \
        : "=r"((r)[0]), "=r"((r)[1]), "=r"((r)[2]), "=r"((r)[3]) : "r"(addr))
#define LDSM4T(r, addr) \
    asm volatile("ldmatrix.sync.aligned.m8n8.x4.trans.shared.b16 {%0,%1,%2,%3}, [%4];" \
        : "=r"((r)[0]), "=r"((r)[1]), "=r"((r)[2]), "=r"((r)[3]) : "r"(addr))
#define MMA_F16(d, a, b) \
    asm volatile("mma.sync.aligned.m16n8k16.row.col.f32.f16.f16.f32 " \
        "{%0,%1,%2,%3},{%4,%5,%6,%7},{%8,%9},{%0,%1,%2,%3};" \
        : "+f"((d)[0]), "+f"((d)[1]), "+f"((d)[2]), "+f"((d)[3]) \
        : "r"((a)[0]), "r"((a)[1]), "r"((a)[2]), "r"((a)[3]), \
          "r"((b)[0]), "r"((b)[1]))

__device__ __forceinline__ float ex2f(float x) {
    float y; asm("ex2.approx.ftz.f32 %0, %1;" : "=f"(y) : "f"(x)); return y;
}
// pack two fp32 -> f16x2 (round-to-nearest)
__device__ __forceinline__ uint32_t pk2h(float v0, float v1) {
    __half2 h = __floats2half2_rn(v0, v1);
    return *reinterpret_cast<uint32_t*>(&h);
}
// fp32 pair -> f16x2 hi + f16x2 lo
__device__ __forceinline__ void split2h(float v0, float v1, uint32_t& hi, uint32_t& lo) {
    __half2 h = __floats2half2_rn(v0, v1);
    float2 hf = __half22float2(h);
    __half2 l = __floats2half2_rn(v0 - hf.x, v1 - hf.y);
    hi = *reinterpret_cast<uint32_t*>(&h);
    lo = *reinterpret_cast<uint32_t*>(&l);
}

#define SC2A (0.125f * 1.4426950408889634f)   // attn scale * log2e, folded into Q

// ---------------------------------------------------------------------------
__global__ void build_cs_kernel(const int* __restrict__ pos, float2* __restrict__ cs)
{
    int idx = blockIdx.x * blockDim.x + threadIdx.x;
    if (idx >= S_ * (DK/2)) return;
    int s = idx >> 5, p = idx & 31;
    float posf = (float)pos[s];
    double e   = (double)(2 * p) / (double)DK;
    float inv  = (float)exp(-e * log(10000.0));
    float ang  = posf * inv;
    cs[idx] = make_float2((float)cos((double)ang), (float)sin((double)ang));
}

// X -> single fp16
__global__ void split_x_kernel(const float* __restrict__ src, __half* __restrict__ dst, int n)
{
    int i = (blockIdx.x * blockDim.x + threadIdx.x) * 8;
    if (i >= n) return;
    float4 a = *(const float4*)(src + i);
    float4 b = *(const float4*)(src + i + 4);
    uint4 o;
    o.x = pk2h(a.x, a.y); o.y = pk2h(a.z, a.w);
    o.z = pk2h(b.x, b.y); o.w = pk2h(b.z, b.w);
    *(uint4*)(dst + i) = o;
}

// all 4 weight matrices -> fp16 hi/lo
__global__ void split_w_kernel(const float* __restrict__ Wq, const float* __restrict__ Wk,
                               const float* __restrict__ Wv, const float* __restrict__ Wo,
                               __half* __restrict__ whi, __half* __restrict__ wlo)
{
    int gid = blockIdx.x * blockDim.x + threadIdx.x;
    int w = gid >> 17;
    size_t i = (size_t)(gid & 131071) * 8;
    const float* src = (w == 0) ? Wq : (w == 1) ? Wk : (w == 2) ? Wv : Wo;
    size_t base = (size_t)w * DM * DM + i;
    float4 a = *(const float4*)(src + i);
    float4 b = *(const float4*)(src + i + 4);
    float v[8] = {a.x, a.y, a.z, a.w, b.x, b.y, b.z, b.w};
    uint4 hp, lp;
    uint32_t* hw = (uint32_t*)&hp;
    uint32_t* lw = (uint32_t*)&lp;
#pragma unroll
    for (int j = 0; j < 4; j++) split2h(v[2*j], v[2*j+1], hw[j], lw[j]);
    *(uint4*)(whi + base) = hp;
    *(uint4*)(wlo + base) = lp;
}

// ---------------------------------------------------------------------------
// fp16 2-product GEMM: Y = X @ (Whi+Wlo)^T. CTA tile 128x64, BK=32, 4 warps
// (64x32 each). 2-stage cp.async.
// ---------------------------------------------------------------------------
#define BKK 32
#define NKB (DM / BKK)
#define SROW 40
#define A_TILE (128 * SROW * 2)                 // 10240
#define B_TILE (64 * SROW * 2)                  // 5120
#define STAGE_BYTES (A_TILE + 2 * B_TILE)       // 20480
#define GSMEM (2 * STAGE_BYTES)                 // 40960
#define OFF_A  0
#define OFF_BH A_TILE
#define OFF_BL (A_TILE + B_TILE)

#define GEMM_PROLOG()                                                         \
    extern __shared__ char sm[];                                              \
    const uint32_t sb = smem_u32(sm);                                         \
    const int tid  = threadIdx.x;                                             \
    const int lane = tid & 31;                                                \
    const int wid  = tid >> 5;                                                \
    const int wm   = (wid & 1) * 64;                                          \
    const int wn   = (wid >> 1) * 32;                                         \
    const int m0   = blockIdx.y * 128;                                        \
    const int n0   = blockIdx.x * 64;

#define LOAD_STAGE(sidx, kb) do {                                             \
    uint32_t sdst = sb + (sidx) * STAGE_BYTES;                                \
    int kofs = (kb) * BKK;                                                    \
    _Pragma("unroll")                                                         \
    for (int i = 0; i < 4; i++) {                                             \
        int id = tid + i * 128;                                               \
        int r = id >> 2, c = (id & 3) * 8;                                    \
        CP16(sdst + OFF_A + (r * SROW + c) * 2,                               \
             A_ + (size_t)(m0 + r) * DM + kofs + c);                          \
    }                                                                         \
    _Pragma("unroll")                                                         \
    for (int i = 0; i < 2; i++) {                                             \
        int id = tid + i * 128;                                               \
        int r = id >> 2, c = (id & 3) * 8;                                    \
        CP16(sdst + OFF_BH + (r * SROW + c) * 2,                              \
             Bhi_ + (size_t)(n0 + r) * DM + kofs + c);                        \
        CP16(sdst + OFF_BL + (r * SROW + c) * 2,                              \
             Blo_ + (size_t)(n0 + r) * DM + kofs + c);                        \
    }                                                                         \
} while (0)

#define GEMM_MAIN()                                                           \
    float acc[4][4][4];                                                       \
    _Pragma("unroll")                                                         \
    for (int i = 0; i < 4; i++)                                               \
        _Pragma("unroll")                                                     \
        for (int j = 0; j < 4; j++)                                           \
            _Pragma("unroll")                                                 \
            for (int q = 0; q < 4; q++) acc[i][j][q] = 0.f;                   \
    LOAD_STAGE(0, 0);                                                         \
    CPCOMMIT();                                                               \
    for (int kb = 0; kb < NKB; kb++) {                                        \
        if (kb + 1 < NKB) { LOAD_STAGE((kb + 1) & 1, kb + 1); CPCOMMIT(); CPWAIT1(); } \
        else              { CPWAIT0(); }                                     \
        __syncthreads();                                                      \
        const uint32_t sst = sb + (kb & 1) * STAGE_BYTES;                     \
        _Pragma("unroll")                                                     \
        for (int kk = 0; kk < 2; kk++) {                                      \
            uint32_t af[4][4], b_h[2][4], b_l[2][4];                          \
            const int ar = wm + (lane & 15);                                  \
            const int ac = kk * 16 + (lane >> 4) * 8;                         \
            _Pragma("unroll")                                                 \
            for (int i = 0; i < 4; i++)                                       \
                LDSM4(af[i], sst + OFF_A + (((ar + i * 16) * SROW + ac) << 1)); \
            const int br = wn + ((lane >> 4) << 3) + (lane & 7);              \
            const int bc = kk * 16 + ((lane >> 3) & 1) * 8;                   \
            _Pragma("unroll")                                                 \
            for (int nb = 0; nb < 2; nb++) {                                  \
                uint32_t bd = sst + (((br + nb * 16) * SROW + bc) << 1);      \
                LDSM4(b_h[nb], bd + OFF_BH);                                  \
                LDSM4(b_l[nb], bd + OFF_BL);                                  \
            }                                                                 \
            _Pragma("unroll")                                                 \
            for (int nb = 0; nb < 2; nb++)                                    \
                _Pragma("unroll")                                             \
                for (int i = 0; i < 4; i++) {                                 \
                    MMA_F16(acc[i][2*nb],   af[i], &b_h[nb][0]);              \
                    MMA_F16(acc[i][2*nb+1], af[i], &b_h[nb][2]);              \
                }                                                             \
            _Pragma("unroll")                                                 \
            for (int nb = 0; nb < 2; nb++)                                    \
                _Pragma("unroll")                                             \
                for (int i = 0; i < 4; i++) {                                 \
                    MMA_F16(acc[i][2*nb],   af[i], &b_l[nb][0]);              \
                    MMA_F16(acc[i][2*nb+1], af[i], &b_l[nb][2]);              \
                }                                                             \
        }                                                                     \
        __syncthreads();                                                      \
    }

// ---- QKV projections: blockIdx.z = 0(Q: rope+scale, single) 1(K: rope, hi/lo) 2(V: hi/lo)
__global__ __launch_bounds__(128, 3)
void gemm_qkv(const __half* __restrict__ X,
              const __half* __restrict__ Whi, const __half* __restrict__ Wlo,
              __half* __restrict__ q,
              __half* __restrict__ khi, __half* __restrict__ klo,
              __half* __restrict__ vhi, __half* __restrict__ vlo,
              const float2* __restrict__ cs)
{
    GEMM_PROLOG();
    const int z = blockIdx.z;
    const __half* A_   = X;
    const __half* Bhi_ = Whi + (size_t)z * DM * DM;
    const __half* Blo_ = Wlo + (size_t)z * DM * DM;
    GEMM_MAIN();

#pragma unroll
    for (int i = 0; i < 4; i++)
#pragma unroll
        for (int j = 0; j < 4; j++) {
            const int col = n0 + wn + j * 8 + (lane & 3) * 2;
#pragma unroll
            for (int h = 0; h < 2; h++) {
                const int row = m0 + wm + i * 16 + (lane >> 2) + h * 8;
                float v0 = acc[i][j][h * 2], v1 = acc[i][j][h * 2 + 1];
                if (z < 2) {   // RoPE for Q,K
                    int s = row & (S_ - 1);
                    float2 cp = cs[s * 32 + ((col & (DK - 1)) >> 1)];
                    float o0 = v0 * cp.x - v1 * cp.y;
                    float o1 = v0 * cp.y + v1 * cp.x;
                    v0 = o0; v1 = o1;
                }
                if (z == 0) {
                    v0 *= SC2A; v1 *= SC2A;
                    *(uint32_t*)(q + (size_t)row * DM + col) = pk2h(v0, v1);
                } else {
                    __half* Yhi = (z == 1) ? khi : vhi;
                    __half* Ylo = (z == 1) ? klo : vlo;
                    uint32_t hp, lp;
                    split2h(v0, v1, hp, lp);
                    *(uint32_t*)(Yhi + (size_t)row * DM + col) = hp;
                    *(uint32_t*)(Ylo + (size_t)row * DM + col) = lp;
                }
            }
        }
}

// ---- O projection: A single fp16 @ Wo hi/lo -> fp32 out
__global__ __launch_bounds__(128, 3)
void gemm_o(const __half* __restrict__ A,
            const __half* __restrict__ Whi, const __half* __restrict__ Wlo,
            float* __restrict__ Y)
{
    GEMM_PROLOG();
    const __half* A_   = A;
    const __half* Bhi_ = Whi;
    const __half* Blo_ = Wlo;
    GEMM_MAIN();

#pragma unroll
    for (int i = 0; i < 4; i++)
#pragma unroll
        for (int j = 0; j < 4; j++) {
            const int col = n0 + wn + j * 8 + (lane & 3) * 2;
#pragma unroll
            for (int h = 0; h < 2; h++) {
                const int row = m0 + wm + i * 16 + (lane >> 2) + h * 8;
                *(float2*)(Y + (size_t)row * DM + col) =
                    make_float2(acc[i][j][h * 2], acc[i][j][h * 2 + 1]);
            }
        }
}

// ---------------------------------------------------------------------------
// fp16 2-product causal flash attention. Q single (pre-scaled), K/V hi+lo,
// P single fp16. CTA = 128 queries, 8 warps x 16 rows, 2-stage KV pipeline.
// ---------------------------------------------------------------------------
#define SP 72
#define QBB (128 * SP * 2)             // 18432 (single Q)
#define KVB (64 * SP * 2)              // 9216
#define STG (4 * KVB)                  // 36864: Khi,Klo,Vhi,Vlo
#define ATT_SMEM (QBB + 2 * STG)       // 92160

__global__ __launch_bounds__(256)
void attn_mma(const __half* __restrict__ Q,
              const __half* __restrict__ Khi, const __half* __restrict__ Klo,
              const __half* __restrict__ Vhi, const __half* __restrict__ Vlo,
              __half* __restrict__ Aout)
{
    extern __shared__ char sm[];
    const uint32_t sb = smem_u32(sm);
    const uint32_t sQ = sb;
    const uint32_t sStage = sb + QBB;

    const int tid = threadIdx.x, lane = tid & 31, wid = tid >> 5;
    const int qb = 15 - blockIdx.x;        // heavy blocks first
    const int bh = blockIdx.y;
    const int b = bh >> 4, h = bh & 15;
    const int wm = wid * 16;
    const size_t rowbase = (size_t)b * S_;
    const int hoff = h * DK;

    // Q tile: 128 rows x 64 cols fp16 = 1024 x 16B chunks, 4 per thread.
    // (round-10 proven indexing: r = id>>3 in [0,128), c = (id&7)*8 in [0,64))
#pragma unroll
    for (int i = 0; i < 4; i++) {
        int id = tid + i * 256;
        int r = id >> 3, c = (id & 7) * 8;
        CP16(sQ + (r * SP + c) * 2,
             Q + (rowbase + qb * 128 + r) * DM + hoff + c);
    }

#define LOAD_KV(sidx, kb_) do {                                               \
    uint32_t dst = sStage + (sidx) * STG;                                     \
    size_t krow0 = rowbase + (size_t)(kb_) * 64;                              \
    _Pragma("unroll")                                                         \
    for (int i = 0; i < 2; i++) {                                             \
        int id = tid + i * 256;                                               \
        int r = id >> 3, c = (id & 7) * 8;                                    \
        size_t g = (krow0 + r) * DM + hoff + c;                               \
        uint32_t so = (r * SP + c) * 2;                                       \
        CP16(dst + 0 * KVB + so, Khi + g);                                    \
        CP16(dst + 1 * KVB + so, Klo + g);                                    \
        CP16(dst + 2 * KVB + so, Vhi + g);                                    \
        CP16(dst + 3 * KVB + so, Vlo + g);                                    \
    }                                                                         \
} while (0)

    LOAD_KV(0, 0);
    CPCOMMIT();

    float m2[2] = {-1e30f, -1e30f}, l[2] = {0.f, 0.f};
    float oacc[8][4];
#pragma unroll
    for (int j = 0; j < 8; j++)
#pragma unroll
        for (int q = 0; q < 4; q++) oacc[j][q] = 0.f;

    uint32_t qf[4][4];   // hoisted Q fragments (single)

    const uint32_t q_off  = ((uint32_t)(wm + (lane & 15)) * SP + (lane >> 4) * 8) * 2;
    const uint32_t k_loff = ((uint32_t)(((lane >> 4) << 3) + (lane & 7)) * SP
                             + ((lane >> 3) & 1) * 8) * 2;
    const uint32_t v_loff = ((uint32_t)(lane & 15) * SP + (lane >> 4) * 8) * 2;

    const int nkb = 2 * qb + 2;

    for (int kb = 0; kb < nkb; kb++) {
        if (kb + 1 < nkb) { LOAD_KV((kb + 1) & 1, kb + 1); CPCOMMIT(); CPWAIT1(); }
        else              { CPWAIT0(); }
        __syncthreads();

        if (kb == 0) {
#pragma unroll
            for (int kc = 0; kc < 4; kc++)
                LDSM4(qf[kc], sQ + q_off + kc * 32);
        }

        const uint32_t sK = sStage + (kb & 1) * STG;
        const uint32_t sV = sK + 2 * KVB;

        // ---- S = Q (Khi + Klo)^T : 2 products
        float sacc[8][4];
#pragma unroll
        for (int j = 0; j < 8; j++)
#pragma unroll
            for (int q = 0; q < 4; q++) sacc[j][q] = 0.f;

#pragma unroll
        for (int kc = 0; kc < 4; kc++) {
            uint32_t kb_h[4][4], kb_l[4][4];
#pragma unroll
            for (int nb = 0; nb < 4; nb++) {
                uint32_t ka = sK + (uint32_t)(nb * 16) * SP * 2 + k_loff + kc * 32;
                LDSM4(kb_h[nb], ka);
                LDSM4(kb_l[nb], ka + KVB);
            }
#pragma unroll
            for (int nb = 0; nb < 4; nb++) {
                MMA_F16(sacc[2*nb],   qf[kc], &kb_h[nb][0]);
                MMA_F16(sacc[2*nb+1], qf[kc], &kb_h[nb][2]);
            }
#pragma unroll
            for (int nb = 0; nb < 4; nb++) {
                MMA_F16(sacc[2*nb],   qf[kc], &kb_l[nb][0]);
                MMA_F16(sacc[2*nb+1], qf[kc], &kb_l[nb][2]);
            }
        }

        // ---- online softmax (base-2; scale folded into Q)
        const int grow0 = qb * 128 + wm + (lane >> 2);
        const bool diag = (kb >= 2 * qb);
        float rmx0 = -1e30f, rmx1 = -1e30f;
        if (diag) {
#pragma unroll
            for (int j = 0; j < 8; j++) {
                int cbase = kb * 64 + j * 8 + 2 * (lane & 3);
#pragma unroll
                for (int e = 0; e < 2; e++) {
                    if (cbase + e > grow0)     sacc[j][e]     = -1e30f;
                    if (cbase + e > grow0 + 8) sacc[j][2 + e] = -1e30f;
                }
            }
        }
#pragma unroll
        for (int j = 0; j < 8; j++) {
            rmx0 = fmaxf(rmx0, fmaxf(sacc[j][0], sacc[j][1]));
            rmx1 = fmaxf(rmx1, fmaxf(sacc[j][2], sacc[j][3]));
        }
        rmx0 = fmaxf(rmx0, __shfl_xor_sync(0xffffffffu, rmx0, 1));
        rmx0 = fmaxf(rmx0, __shfl_xor_sync(0xffffffffu, rmx0, 2));
        rmx1 = fmaxf(rmx1, __shfl_xor_sync(0xffffffffu, rmx1, 1));
        rmx1 = fmaxf(rmx1, __shfl_xor_sync(0xffffffffu, rmx1, 2));
        float mn0 = fmaxf(m2[0], rmx0), mn1 = fmaxf(m2[1], rmx1);

        float rs0 = 0.f, rs1 = 0.f;
#pragma unroll
        for (int j = 0; j < 8; j++) {
#pragma unroll
            for (int e = 0; e < 2; e++) {
                float p0 = ex2f(sacc[j][e] - mn0);
                float p1 = ex2f(sacc[j][2 + e] - mn1);
                sacc[j][e] = p0; sacc[j][2 + e] = p1;
                rs0 += p0; rs1 += p1;
            }
        }
        rs0 += __shfl_xor_sync(0xffffffffu, rs0, 1);
        rs0 += __shfl_xor_sync(0xffffffffu, rs0, 2);
        rs1 += __shfl_xor_sync(0xffffffffu, rs1, 1);
        rs1 += __shfl_xor_sync(0xffffffffu, rs1, 2);

        float al0 = ex2f(m2[0] - mn0), al1 = ex2f(m2[1] - mn1);
        l[0] = l[0] * al0 + rs0;
        l[1] = l[1] * al1 + rs1;
        m2[0] = mn0; m2[1] = mn1;
#pragma unroll
        for (int j = 0; j < 8; j++) {
            oacc[j][0] *= al0; oacc[j][1] *= al0;
            oacc[j][2] *= al1; oacc[j][3] *= al1;
        }

        // ---- O += P (Vhi + Vlo) : P single fp16, 2 products
#pragma unroll
        for (int g = 0; g < 4; g++) {
            uint32_t pa[4];
            pa[0] = pk2h(sacc[2*g][0],   sacc[2*g][1]);
            pa[1] = pk2h(sacc[2*g][2],   sacc[2*g][3]);
            pa[2] = pk2h(sacc[2*g+1][0], sacc[2*g+1][1]);
            pa[3] = pk2h(sacc[2*g+1][2], sacc[2*g+1][3]);
            uint32_t vb_h[4][4], vb_l[4][4];
#pragma unroll
            for (int nb = 0; nb < 4; nb++) {
                uint32_t va = sV + (uint32_t)(g * 16) * SP * 2 + v_loff + nb * 32;
                LDSM4T(vb_h[nb], va);
                LDSM4T(vb_l[nb], va + KVB);
            }
#pragma unroll
            for (int nb = 0; nb < 4; nb++) {
                MMA_F16(oacc[2*nb],   pa, &vb_h[nb][0]);
                MMA_F16(oacc[2*nb+1], pa, &vb_h[nb][2]);
            }
#pragma unroll
            for (int nb = 0; nb < 4; nb++) {
                MMA_F16(oacc[2*nb],   pa, &vb_l[nb][0]);
                MMA_F16(oacc[2*nb+1], pa, &vb_l[nb][2]);
            }
        }
        __syncthreads();   // all warps done with stage kb before reload
    }
#undef LOAD_KV

    // ---- epilogue: normalize, store single fp16
    float inv0 = 1.f / l[0], inv1 = 1.f / l[1];
    const size_t row0 = rowbase + (size_t)qb * 128 + wm + (lane >> 2);
#pragma unroll
    for (int j = 0; j < 8; j++) {
        const int col = hoff + j * 8 + 2 * (lane & 3);
        *(uint32_t*)(Aout + row0 * DM + col) =
            pk2h(oacc[j][0] * inv0, oacc[j][1] * inv0);
        *(uint32_t*)(Aout + (row0 + 8) * DM + col) =
            pk2h(oacc[j][2] * inv1, oacc[j][3] * inv1);
    }
}

// ---------------------------------------------------------------------------
extern "C" void kernel_launch(void* const* d_in, const int* in_sizes, int n_in,
                              void* d_out, int out_size)
{
    const float *x, *Wq, *Wk, *Wv, *Wo;
    const int* pos;
    if (in_sizes[0] == MTOT * DM) {            // setup_inputs dict order
        x   = (const float*)d_in[0];
        pos = (const int*)  d_in[1];
        Wq  = (const float*)d_in[2];
        Wk  = (const float*)d_in[3];
        Wv  = (const float*)d_in[4];
        Wo  = (const float*)d_in[5];
    } else {                                   // name-sorted order
        Wk  = (const float*)d_in[0];
        Wo  = (const float*)d_in[1];
        Wq  = (const float*)d_in[2];
        Wv  = (const float*)d_in[3];
        pos = (const int*)  d_in[4];
        x   = (const float*)d_in[5];
    }
    float* out = (float*)d_out;

    float2* cs;
    __half *xh, *whi, *wlo, *q, *khi, *klo, *vhi, *vlo;
    cudaGetSymbolAddress((void**)&cs,  g_cs);
    cudaGetSymbolAddress((void**)&xh,  g_x);
    cudaGetSymbolAddress((void**)&whi, g_whi);
    cudaGetSymbolAddress((void**)&wlo, g_wlo);
    cudaGetSymbolAddress((void**)&q,   g_q);
    cudaGetSymbolAddress((void**)&khi, g_khi);
    cudaGetSymbolAddress((void**)&klo, g_klo);
    cudaGetSymbolAddress((void**)&vhi, g_vhi);
    cudaGetSymbolAddress((void**)&vlo, g_vlo);

    const int NX = MTOT * DM, NW = DM * DM;

    build_cs_kernel<<<(S_ * (DK/2) + 255) / 256, 256>>>(pos, cs);          // 0
    split_x_kernel<<<NX / 8 / 256, 256>>>(x, xh, NX);                      // 1
    split_w_kernel<<<4 * NW / 8 / 256, 256>>>(Wq, Wk, Wv, Wo, whi, wlo);   // 2

    cudaFuncSetAttribute(gemm_qkv, cudaFuncAttributeMaxDynamicSharedMemorySize, GSMEM);
    cudaFuncSetAttribute(gemm_o,   cudaFuncAttributeMaxDynamicSharedMemorySize, GSMEM);
    cudaFuncSetAttribute(attn_mma, cudaFuncAttributeMaxDynamicSharedMemorySize, ATT_SMEM);

    dim3 gq(DM / 64, MTOT / 128, 3);    // (16, 32, 3)
    gemm_qkv<<<gq, 128, GSMEM>>>(xh, whi, wlo, q, khi, klo, vhi, vlo, cs); // 3

    attn_mma<<<dim3(16, B_ * NH), 256, ATT_SMEM>>>(q, khi, klo,
                                                   vhi, vlo, xh);          // 4

    dim3 gg(DM / 64, MTOT / 128);       // (16, 32)
    gemm_o<<<gg, 128, GSMEM>>>(xh, whi + 3 * (size_t)NW,
                               wlo + 3 * (size_t)NW, out);                 // 5 <- profiled
}

// round 14
// speedup vs baseline: 2.3263x; 1.5834x over previous
#include <cuda_runtime.h>
#include <cuda_fp16.h>
#include <math.h>
#include <stdint.h>

#define DM 1024
#define NH 16
#define DK 64
#define B_ 2
#define S_ 2048
#define MTOT (B_*S_)   // 4096

// ---------------- scratch (device globals: allocation-free) ----------------
// pure fp16: every tensor single-precision-half, fp32 accumulate in MMA.
__device__ float2 g_cs[S_ * (DK/2)];
__device__ __half g_x[MTOT*DM];          // X fp16 (reused for attn out A)
__device__ __half g_w[4][DM*DM];
__device__ __half g_q[MTOT*DM];          // Q (pre-scaled by 0.125*log2e)
__device__ __half g_k[MTOT*DM];
__device__ __half g_v[MTOT*DM];

// ---------------- family-portable PTX helpers ----------------
__device__ __forceinline__ uint32_t smem_u32(const void* p) {
    uint32_t a;
    asm("{ .reg .u64 t; cvta.to.shared.u64 t, %1; cvt.u32.u64 %0, t; }"
        : "=r"(a) : "l"(p));
    return a;
}
#define CP16(saddr, gptr) \
    asm volatile("cp.async.cg.shared.global [%0], [%1], 16;" :: "r"(saddr), "l"(gptr))
#define CPCOMMIT() asm volatile("cp.async.commit_group;" ::: "memory")
#define CPWAIT0()  asm volatile("cp.async.wait_group 0;" ::: "memory")
#define CPWAIT1()  asm volatile("cp.async.wait_group 1;" ::: "memory")
#define LDSM4(r, addr) \
    asm volatile("ldmatrix.sync.aligned.m8n8.x4.shared.b16 {%0,%1,%2,%3}, [%4];" \
        : "=r"((r)[0]), "=r"((r)[1]), "=r"((r)[2]), "=r"((r)[3]) : "r"(addr))
#define LDSM4T(r, addr) \
    asm volatile("ldmatrix.sync.aligned.m8n8.x4.trans.shared.b16 {%0,%1,%2,%3}, [%4];" \
        : "=r"((r)[0]), "=r"((r)[1]), "=r"((r)[2]), "=r"((r)[3]) : "r"(addr))
#define MMA_F16(d, a, b) \
    asm volatile("mma.sync.aligned.m16n8k16.row.col.f32.f16.f16.f32 " \
        "{%0,%1,%2,%3},{%4,%5,%6,%7},{%8,%9},{%0,%1,%2,%3};" \
        : "+f"((d)[0]), "+f"((d)[1]), "+f"((d)[2]), "+f"((d)[3]) \
        : "r"((a)[0]), "r"((a)[1]), "r"((a)[2]), "r"((a)[3]), \
          "r"((b)[0]), "r"((b)[1]))

__device__ __forceinline__ float ex2f(float x) {
    float y; asm("ex2.approx.ftz.f32 %0, %1;" : "=f"(y) : "f"(x)); return y;
}
__device__ __forceinline__ uint32_t pk2h(float v0, float v1) {
    __half2 h = __floats2half2_rn(v0, v1);
    return *reinterpret_cast<uint32_t*>(&h);
}

#define SC2A (0.125f * 1.4426950408889634f)   // attn scale * log2e, folded into Q

// ---------------------------------------------------------------------------
__global__ void build_cs_kernel(const int* __restrict__ pos, float2* __restrict__ cs)
{
    int idx = blockIdx.x * blockDim.x + threadIdx.x;
    if (idx >= S_ * (DK/2)) return;
    int s = idx >> 5, p = idx & 31;
    float posf = (float)pos[s];
    double e   = (double)(2 * p) / (double)DK;
    float inv  = (float)exp(-e * log(10000.0));
    float ang  = posf * inv;
    cs[idx] = make_float2((float)cos((double)ang), (float)sin((double)ang));
}

// fp32 -> fp16 convert (X)
__global__ void conv_x_kernel(const float* __restrict__ src, __half* __restrict__ dst, int n)
{
    int i = (blockIdx.x * blockDim.x + threadIdx.x) * 8;
    if (i >= n) return;
    float4 a = *(const float4*)(src + i);
    float4 b = *(const float4*)(src + i + 4);
    uint4 o;
    o.x = pk2h(a.x, a.y); o.y = pk2h(a.z, a.w);
    o.z = pk2h(b.x, b.y); o.w = pk2h(b.z, b.w);
    *(uint4*)(dst + i) = o;
}

// all 4 weight matrices -> fp16
__global__ void conv_w_kernel(const float* __restrict__ Wq, const float* __restrict__ Wk,
                              const float* __restrict__ Wv, const float* __restrict__ Wo,
                              __half* __restrict__ w)
{
    int gid = blockIdx.x * blockDim.x + threadIdx.x;
    int wsel = gid >> 17;                 // DM*DM/8 = 131072
    size_t i = (size_t)(gid & 131071) * 8;
    const float* src = (wsel == 0) ? Wq : (wsel == 1) ? Wk : (wsel == 2) ? Wv : Wo;
    size_t base = (size_t)wsel * DM * DM + i;
    float4 a = *(const float4*)(src + i);
    float4 b = *(const float4*)(src + i + 4);
    uint4 o;
    o.x = pk2h(a.x, a.y); o.y = pk2h(a.z, a.w);
    o.z = pk2h(b.x, b.y); o.w = pk2h(b.z, b.w);
    *(uint4*)(w + base) = o;
}

// ---------------------------------------------------------------------------
// fp16 GEMM: Y = X @ W^T (single product). CTA tile 128x64, BK=32, 4 warps
// (64x32 each). 2-stage cp.async.
// ---------------------------------------------------------------------------
#define BKK 32
#define NKB (DM / BKK)
#define SROW 40
#define A_TILE (128 * SROW * 2)                 // 10240
#define B_TILE (64 * SROW * 2)                  // 5120
#define STAGE_BYTES (A_TILE + B_TILE)           // 15360
#define GSMEM (2 * STAGE_BYTES)                 // 30720
#define OFF_A  0
#define OFF_B  A_TILE

#define GEMM_PROLOG()                                                         \
    extern __shared__ char sm[];                                              \
    const uint32_t sb = smem_u32(sm);                                         \
    const int tid  = threadIdx.x;                                             \
    const int lane = tid & 31;                                                \
    const int wid  = tid >> 5;                                                \
    const int wm   = (wid & 1) * 64;                                          \
    const int wn   = (wid >> 1) * 32;                                         \
    const int m0   = blockIdx.y * 128;                                        \
    const int n0   = blockIdx.x * 64;

#define LOAD_STAGE(sidx, kb) do {                                             \
    uint32_t sdst = sb + (sidx) * STAGE_BYTES;                                \
    int kofs = (kb) * BKK;                                                    \
    _Pragma("unroll")                                                         \
    for (int i = 0; i < 4; i++) {                                             \
        int id = tid + i * 128;                                               \
        int r = id >> 2, c = (id & 3) * 8;                                    \
        CP16(sdst + OFF_A + (r * SROW + c) * 2,                               \
             Ag_ + (size_t)(m0 + r) * DM + kofs + c);                         \
    }                                                                         \
    _Pragma("unroll")                                                         \
    for (int i = 0; i < 2; i++) {                                             \
        int id = tid + i * 128;                                               \
        int r = id >> 2, c = (id & 3) * 8;                                    \
        CP16(sdst + OFF_B + (r * SROW + c) * 2,                               \
             Bg_ + (size_t)(n0 + r) * DM + kofs + c);                         \
    }                                                                         \
} while (0)

#define GEMM_MAIN()                                                           \
    float acc[4][4][4];                                                       \
    _Pragma("unroll")                                                         \
    for (int i = 0; i < 4; i++)                                               \
        _Pragma("unroll")                                                     \
        for (int j = 0; j < 4; j++)                                           \
            _Pragma("unroll")                                                 \
            for (int q = 0; q < 4; q++) acc[i][j][q] = 0.f;                   \
    LOAD_STAGE(0, 0);                                                         \
    CPCOMMIT();                                                               \
    for (int kb = 0; kb < NKB; kb++) {                                        \
        if (kb + 1 < NKB) { LOAD_STAGE((kb + 1) & 1, kb + 1); CPCOMMIT(); CPWAIT1(); } \
        else              { CPWAIT0(); }                                     \
        __syncthreads();                                                      \
        const uint32_t sst = sb + (kb & 1) * STAGE_BYTES;                     \
        _Pragma("unroll")                                                     \
        for (int kk = 0; kk < 2; kk++) {                                      \
            uint32_t af[4][4], bf[2][4];                                      \
            const int ar = wm + (lane & 15);                                  \
            const int ac = kk * 16 + (lane >> 4) * 8;                         \
            _Pragma("unroll")                                                 \
            for (int i = 0; i < 4; i++)                                       \
                LDSM4(af[i], sst + OFF_A + (((ar + i * 16) * SROW + ac) << 1)); \
            const int br = wn + ((lane >> 4) << 3) + (lane & 7);              \
            const int bc = kk * 16 + ((lane >> 3) & 1) * 8;                   \
            _Pragma("unroll")                                                 \
            for (int nb = 0; nb < 2; nb++)                                    \
                LDSM4(bf[nb], sst + OFF_B + (((br + nb * 16) * SROW + bc) << 1)); \
            _Pragma("unroll")                                                 \
            for (int nb = 0; nb < 2; nb++)                                    \
                _Pragma("unroll")                                             \
                for (int i = 0; i < 4; i++) {                                 \
                    MMA_F16(acc[i][2*nb],   af[i], &bf[nb][0]);               \
                    MMA_F16(acc[i][2*nb+1], af[i], &bf[nb][2]);               \
                }                                                             \
        }                                                                     \
        __syncthreads();                                                      \
    }

// ---- QKV projections: blockIdx.z = 0(Q: rope+scale) 1(K: rope) 2(V)
__global__ __launch_bounds__(128, 3)
void gemm_qkv(const __half* __restrict__ X, const __half* __restrict__ W,
              __half* __restrict__ q, __half* __restrict__ k, __half* __restrict__ v,
              const float2* __restrict__ cs)
{
    GEMM_PROLOG();
    const int z = blockIdx.z;
    const __half* Ag_ = X;
    const __half* Bg_ = W + (size_t)z * DM * DM;
    GEMM_MAIN();

    __half* Y = (z == 0) ? q : (z == 1) ? k : v;
#pragma unroll
    for (int i = 0; i < 4; i++)
#pragma unroll
        for (int j = 0; j < 4; j++) {
            const int col = n0 + wn + j * 8 + (lane & 3) * 2;
#pragma unroll
            for (int h = 0; h < 2; h++) {
                const int row = m0 + wm + i * 16 + (lane >> 2) + h * 8;
                float v0 = acc[i][j][h * 2], v1 = acc[i][j][h * 2 + 1];
                if (z < 2) {   // RoPE for Q,K
                    int s = row & (S_ - 1);
                    float2 cp = cs[s * 32 + ((col & (DK - 1)) >> 1)];
                    float o0 = v0 * cp.x - v1 * cp.y;
                    float o1 = v0 * cp.y + v1 * cp.x;
                    v0 = o0; v1 = o1;
                }
                if (z == 0) { v0 *= SC2A; v1 *= SC2A; }
                *(uint32_t*)(Y + (size_t)row * DM + col) = pk2h(v0, v1);
            }
        }
}

// ---- O projection: A fp16 @ Wo fp16 -> fp32 out
__global__ __launch_bounds__(128, 3)
void gemm_o(const __half* __restrict__ A, const __half* __restrict__ W,
            float* __restrict__ Y)
{
    GEMM_PROLOG();
    const __half* Ag_ = A;
    const __half* Bg_ = W;
    GEMM_MAIN();

#pragma unroll
    for (int i = 0; i < 4; i++)
#pragma unroll
        for (int j = 0; j < 4; j++) {
            const int col = n0 + wn + j * 8 + (lane & 3) * 2;
#pragma unroll
            for (int h = 0; h < 2; h++) {
                const int row = m0 + wm + i * 16 + (lane >> 2) + h * 8;
                *(float2*)(Y + (size_t)row * DM + col) =
                    make_float2(acc[i][j][h * 2], acc[i][j][h * 2 + 1]);
            }
        }
}

// ---------------------------------------------------------------------------
// Pure-fp16 causal flash attention. Q pre-scaled; K, V, P single fp16.
// CTA = 128 queries, 8 warps x 16 rows, 2-stage KV pipeline.
// ---------------------------------------------------------------------------
#define SP 72
#define QBB (128 * SP * 2)             // 18432
#define KVB (64 * SP * 2)              // 9216
#define STG (2 * KVB)                  // 18432: K, V
#define ATT_SMEM (QBB + 2 * STG)       // 55296

__global__ __launch_bounds__(256)
void attn_mma(const __half* __restrict__ Q, const __half* __restrict__ K,
              const __half* __restrict__ V, __half* __restrict__ Aout)
{
    extern __shared__ char sm[];
    const uint32_t sb = smem_u32(sm);
    const uint32_t sQ = sb;
    const uint32_t sStage = sb + QBB;

    const int tid = threadIdx.x, lane = tid & 31, wid = tid >> 5;
    const int qb = 15 - blockIdx.x;        // heavy blocks first
    const int bh = blockIdx.y;
    const int b = bh >> 4, h = bh & 15;
    const int wm = wid * 16;
    const size_t rowbase = (size_t)b * S_;
    const int hoff = h * DK;

    // Q tile: 128 rows x 64 cols fp16 (proven indexing)
#pragma unroll
    for (int i = 0; i < 4; i++) {
        int id = tid + i * 256;
        int r = id >> 3, c = (id & 7) * 8;
        CP16(sQ + (r * SP + c) * 2,
             Q + (rowbase + qb * 128 + r) * DM + hoff + c);
    }

#define LOAD_KV(sidx, kb_) do {                                               \
    uint32_t dst = sStage + (sidx) * STG;                                     \
    size_t krow0 = rowbase + (size_t)(kb_) * 64;                              \
    _Pragma("unroll")                                                         \
    for (int i = 0; i < 2; i++) {                                             \
        int id = tid + i * 256;                                               \
        int r = id >> 3, c = (id & 7) * 8;                                    \
        size_t g = (krow0 + r) * DM + hoff + c;                               \
        uint32_t so = (r * SP + c) * 2;                                       \
        CP16(dst + 0 * KVB + so, K + g);                                      \
        CP16(dst + 1 * KVB + so, V + g);                                      \
    }                                                                         \
} while (0)

    LOAD_KV(0, 0);
    CPCOMMIT();

    float m2[2] = {-1e30f, -1e30f}, l[2] = {0.f, 0.f};
    float oacc[8][4];
#pragma unroll
    for (int j = 0; j < 8; j++)
#pragma unroll
        for (int q = 0; q < 4; q++) oacc[j][q] = 0.f;

    uint32_t qf[4][4];   // hoisted Q fragments

    const uint32_t q_off  = ((uint32_t)(wm + (lane & 15)) * SP + (lane >> 4) * 8) * 2;
    const uint32_t k_loff = ((uint32_t)(((lane >> 4) << 3) + (lane & 7)) * SP
                             + ((lane >> 3) & 1) * 8) * 2;
    const uint32_t v_loff = ((uint32_t)(lane & 15) * SP + (lane >> 4) * 8) * 2;

    const int nkb = 2 * qb + 2;

    for (int kb = 0; kb < nkb; kb++) {
        if (kb + 1 < nkb) { LOAD_KV((kb + 1) & 1, kb + 1); CPCOMMIT(); CPWAIT1(); }
        else              { CPWAIT0(); }
        __syncthreads();

        if (kb == 0) {
#pragma unroll
            for (int kc = 0; kc < 4; kc++)
                LDSM4(qf[kc], sQ + q_off + kc * 32);
        }

        const uint32_t sK = sStage + (kb & 1) * STG;
        const uint32_t sV = sK + KVB;

        // ---- S = Q K^T (single product)
        float sacc[8][4];
#pragma unroll
        for (int j = 0; j < 8; j++)
#pragma unroll
            for (int q = 0; q < 4; q++) sacc[j][q] = 0.f;

#pragma unroll
        for (int kc = 0; kc < 4; kc++) {
            uint32_t kf[4][4];
#pragma unroll
            for (int nb = 0; nb < 4; nb++)
                LDSM4(kf[nb], sK + (uint32_t)(nb * 16) * SP * 2 + k_loff + kc * 32);
#pragma unroll
            for (int nb = 0; nb < 4; nb++) {
                MMA_F16(sacc[2*nb],   qf[kc], &kf[nb][0]);
                MMA_F16(sacc[2*nb+1], qf[kc], &kf[nb][2]);
            }
        }

        // ---- online softmax (base-2; scale folded into Q)
        const int grow0 = qb * 128 + wm + (lane >> 2);
        const bool diag = (kb >= 2 * qb);
        float rmx0 = -1e30f, rmx1 = -1e30f;
        if (diag) {
#pragma unroll
            for (int j = 0; j < 8; j++) {
                int cbase = kb * 64 + j * 8 + 2 * (lane & 3);
#pragma unroll
                for (int e = 0; e < 2; e++) {
                    if (cbase + e > grow0)     sacc[j][e]     = -1e30f;
                    if (cbase + e > grow0 + 8) sacc[j][2 + e] = -1e30f;
                }
            }
        }
#pragma unroll
        for (int j = 0; j < 8; j++) {
            rmx0 = fmaxf(rmx0, fmaxf(sacc[j][0], sacc[j][1]));
            rmx1 = fmaxf(rmx1, fmaxf(sacc[j][2], sacc[j][3]));
        }
        rmx0 = fmaxf(rmx0, __shfl_xor_sync(0xffffffffu, rmx0, 1));
        rmx0 = fmaxf(rmx0, __shfl_xor_sync(0xffffffffu, rmx0, 2));
        rmx1 = fmaxf(rmx1, __shfl_xor_sync(0xffffffffu, rmx1, 1));
        rmx1 = fmaxf(rmx1, __shfl_xor_sync(0xffffffffu, rmx1, 2));
        float mn0 = fmaxf(m2[0], rmx0), mn1 = fmaxf(m2[1], rmx1);

        float rs0 = 0.f, rs1 = 0.f;
#pragma unroll
        for (int j = 0; j < 8; j++) {
#pragma unroll
            for (int e = 0; e < 2; e++) {
                float p0 = ex2f(sacc[j][e] - mn0);
                float p1 = ex2f(sacc[j][2 + e] - mn1);
                sacc[j][e] = p0; sacc[j][2 + e] = p1;
                rs0 += p0; rs1 += p1;
            }
        }
        rs0 += __shfl_xor_sync(0xffffffffu, rs0, 1);
        rs0 += __shfl_xor_sync(0xffffffffu, rs0, 2);
        rs1 += __shfl_xor_sync(0xffffffffu, rs1, 1);
        rs1 += __shfl_xor_sync(0xffffffffu, rs1, 2);

        float al0 = ex2f(m2[0] - mn0), al1 = ex2f(m2[1] - mn1);
        l[0] = l[0] * al0 + rs0;
        l[1] = l[1] * al1 + rs1;
        m2[0] = mn0; m2[1] = mn1;
#pragma unroll
        for (int j = 0; j < 8; j++) {
            oacc[j][0] *= al0; oacc[j][1] *= al0;
            oacc[j][2] *= al1; oacc[j][3] *= al1;
        }

        // ---- O += P V (single product)
#pragma unroll
        for (int g = 0; g < 4; g++) {
            uint32_t pa[4];
            pa[0] = pk2h(sacc[2*g][0],   sacc[2*g][1]);
            pa[1] = pk2h(sacc[2*g][2],   sacc[2*g][3]);
            pa[2] = pk2h(sacc[2*g+1][0], sacc[2*g+1][1]);
            pa[3] = pk2h(sacc[2*g+1][2], sacc[2*g+1][3]);
            uint32_t vf[4][4];
#pragma unroll
            for (int nb = 0; nb < 4; nb++)
                LDSM4T(vf[nb], sV + (uint32_t)(g * 16) * SP * 2 + v_loff + nb * 32);
#pragma unroll
            for (int nb = 0; nb < 4; nb++) {
                MMA_F16(oacc[2*nb],   pa, &vf[nb][0]);
                MMA_F16(oacc[2*nb+1], pa, &vf[nb][2]);
            }
        }
        __syncthreads();   // all warps done with stage kb before reload
    }
#undef LOAD_KV

    // ---- epilogue: normalize, store fp16
    float inv0 = 1.f / l[0], inv1 = 1.f / l[1];
    const size_t row0 = rowbase + (size_t)qb * 128 + wm + (lane >> 2);
#pragma unroll
    for (int j = 0; j < 8; j++) {
        const int col = hoff + j * 8 + 2 * (lane & 3);
        *(uint32_t*)(Aout + row0 * DM + col) =
            pk2h(oacc[j][0] * inv0, oacc[j][1] * inv0);
        *(uint32_t*)(Aout + (row0 + 8) * DM + col) =
            pk2h(oacc[j][2] * inv1, oacc[j][3] * inv1);
    }
}

// ---------------------------------------------------------------------------
extern "C" void kernel_launch(void* const* d_in, const int* in_sizes, int n_in,
                              void* d_out, int out_size)
{
    const float *x, *Wq, *Wk, *Wv, *Wo;
    const int* pos;
    if (in_sizes[0] == MTOT * DM) {            // setup_inputs dict order
        x   = (const float*)d_in[0];
        pos = (const int*)  d_in[1];
        Wq  = (const float*)d_in[2];
        Wk  = (const float*)d_in[3];
        Wv  = (const float*)d_in[4];
        Wo  = (const float*)d_in[5];
    } else {                                   // name-sorted order
        Wk  = (const float*)d_in[0];
        Wo  = (const float*)d_in[1];
        Wq  = (const float*)d_in[2];
        Wv  = (const float*)d_in[3];
        pos = (const int*)  d_in[4];
        x   = (const float*)d_in[5];
    }
    float* out = (float*)d_out;

    float2* cs;
    __half *xh, *w, *q, *k, *v;
    cudaGetSymbolAddress((void**)&cs, g_cs);
    cudaGetSymbolAddress((void**)&xh, g_x);
    cudaGetSymbolAddress((void**)&w,  g_w);
    cudaGetSymbolAddress((void**)&q,  g_q);
    cudaGetSymbolAddress((void**)&k,  g_k);
    cudaGetSymbolAddress((void**)&v,  g_v);

    const int NX = MTOT * DM, NW = DM * DM;

    build_cs_kernel<<<(S_ * (DK/2) + 255) / 256, 256>>>(pos, cs);          // 0
    conv_x_kernel<<<NX / 8 / 256, 256>>>(x, xh, NX);                       // 1
    conv_w_kernel<<<4 * NW / 8 / 256, 256>>>(Wq, Wk, Wv, Wo, w);           // 2

    cudaFuncSetAttribute(gemm_qkv, cudaFuncAttributeMaxDynamicSharedMemorySize, GSMEM);
    cudaFuncSetAttribute(gemm_o,   cudaFuncAttributeMaxDynamicSharedMemorySize, GSMEM);
    cudaFuncSetAttribute(attn_mma, cudaFuncAttributeMaxDynamicSharedMemorySize, ATT_SMEM);

    dim3 gq(DM / 64, MTOT / 128, 3);    // (16, 32, 3)
    gemm_qkv<<<gq, 128, GSMEM>>>(xh, w, q, k, v, cs);                      // 3

    attn_mma<<<dim3(16, B_ * NH), 256, ATT_SMEM>>>(q, k, v, xh);           // 4

    dim3 gg(DM / 64, MTOT / 128);       // (16, 32)
    gemm_o<<<gg, 128, GSMEM>>>(xh, w + 3 * (size_t)NW, out);               // 5 <- profiled
}